// round 11
// baseline (speedup 1.0000x reference)
#include <cuda_runtime.h>
#include <cuda_bf16.h>
#include <cuda_fp16.h>
#include <math.h>

#define N_IMG 512
#define N_ANGLES 180
#define N_PAIRS 90
#define C_HALF 255.5f

// Fully padded frame: sample coords span [-105.9, 616.9]; offset +106 ->
// floor indices in [0, 722], +1 tap <= 723.
#define W    728
#define OFF  106

#define BLOCKS 888                      // 6 blocks/SM x 148 SMs: ONE wave
#define ITEMS  (N_PAIRS * 64)           // item = (angle-pair, 8-det tile); 5760

// Combined cells, one uint4 (= 4 x half2) per cell:
//   x = (E(r,c),   E(r,c+1))    y = (E(r+1,c), E(r+1,c+1))   E = padded img
//   z = (F(r,c),   F(r,c+1))    w = (F(r+1,c), F(r+1,c+1))   F = padded rot90
// rot90[p,q] = img[511-q, p] (exact grid rotation): angle a and a+90 share
// one sampling lattice; out[:,a] uses E-taps, out[:,a+90] uses F-taps.
// g_T holds the transposed views (used for steep base angles).
__device__ uint4 g_N[W * W];
__device__ uint4 g_T[W * W];

// Per-pair constants: ANG0 = (Au, Bu, Aw, Bw) [cu = Au*x+Bu, cw = Aw*x+Bw]
//                     ANG1 = (au, aw, useT, 0)
__device__ float4 g_ANG0[N_PAIRS];
__device__ float4 g_ANG1[N_PAIRS];

__device__ __forceinline__ unsigned pack_h2(float lo, float hi) {
    __half2 h = __floats2half2_rn(lo, hi);
    return *reinterpret_cast<unsigned*>(&h);
}

// Tiled prep: block (bx,by) builds the 32x32 output region at
// (r0,c0) = (32*by, 32*bx) of BOTH tables with coalesced traffic.
__global__ void __launch_bounds__(256) prep_kernel(const float* __restrict__ img,
                                                   const int* __restrict__ angles) {
    const int tid = threadIdx.x;
    const int r0  = blockIdx.y * 32;
    const int c0  = blockIdx.x * 32;
    const int rr0 = r0 - OFF, cc0 = c0 - OFF;

    if (blockIdx.x == 0 && blockIdx.y == 0 && tid < N_PAIRS) {
        float t  = (float)angles[tid] * (float)(3.14159265358979323846 / 180.0);
        float co = cosf(t);
        float si = sinf(t);
        bool useT = fabsf(si) > fabsf(co);
        float au = useT ? co : si;
        float aw = useT ? si : co;
        float Au = useT ? -si : co;
        float Bu = (C_HALF + (float)OFF) - au * C_HALF;
        float Aw = useT ? co : -si;
        float Bw = (C_HALF + (float)OFF) - aw * C_HALF;
        g_ANG0[tid] = make_float4(Au, Bu, Aw, Bw);
        g_ANG1[tid] = make_float4(au, aw, useT ? 1.f : 0.f, 0.f);
    }

    __shared__ float sE [33][35];
    __shared__ float sET[33][35];
    __shared__ float sF [33][35];
    __shared__ float sFT[33][35];

    for (int i = tid; i < 33 * 33; i += 256) {
        const int lr = i / 33, lc = i - lr * 33;
        const int rE = rr0 + lr, cE = cc0 + lc;
        sE[lr][lc] = (rE >= 0 && rE < N_IMG && cE >= 0 && cE < N_IMG)
                     ? img[rE * N_IMG + cE] : 0.f;
        const int rQ = (N_IMG - 1) - rE;
        sFT[lr][lc] = (rQ >= 0 && rQ < N_IMG && cE >= 0 && cE < N_IMG)
                      ? img[rQ * N_IMG + cE] : 0.f;
        const int rowT = cc0 + lr, colT = rr0 + lc;
        sET[lc][lr] = (rowT >= 0 && rowT < N_IMG && colT >= 0 && colT < N_IMG)
                      ? img[rowT * N_IMG + colT] : 0.f;
        const int rowF = (N_IMG - 1) - rowT;
        sF[lc][lr]  = (rowF >= 0 && rowF < N_IMG && colT >= 0 && colT < N_IMG)
                      ? img[rowF * N_IMG + colT] : 0.f;
    }
    __syncthreads();

    for (int i = tid; i < 32 * 32; i += 256) {
        const int lr = i >> 5, lc = i & 31;
        const int r = r0 + lr, c = c0 + lc;
        if (r >= W || c >= W) continue;
        const int idx = r * W + c;
        uint4 qn;
        qn.x = pack_h2(sE [lr][lc], sE [lr][lc + 1]);
        qn.y = pack_h2(sE [lr + 1][lc], sE [lr + 1][lc + 1]);
        qn.z = pack_h2(sF [lr][lc], sF [lr][lc + 1]);
        qn.w = pack_h2(sF [lr + 1][lc], sF [lr + 1][lc + 1]);
        g_N[idx] = qn;
        uint4 qt;
        qt.x = pack_h2(sET[lr][lc], sET[lr][lc + 1]);
        qt.y = pack_h2(sET[lr + 1][lc], sET[lr + 1][lc + 1]);
        qt.z = pack_h2(sFT[lr][lc], sFT[lr][lc + 1]);
        qt.w = pack_h2(sFT[lr + 1][lc], sFT[lr + 1][lc + 1]);
        g_T[idx] = qt;
    }
}

// ---- f32x2 packed helpers (sm_103a) ----
typedef unsigned long long u64t;
__device__ __forceinline__ u64t pk2(float lo, float hi) {
    u64t r; asm("mov.b64 %0, {%1, %2};" : "=l"(r) : "f"(lo), "f"(hi)); return r;
}
__device__ __forceinline__ void upk2(u64t v, float& lo, float& hi) {
    asm("mov.b64 {%0, %1}, %2;" : "=f"(lo), "=f"(hi) : "l"(v));
}
__device__ __forceinline__ u64t add2(u64t a, u64t b) {
    u64t r; asm("add.rn.f32x2 %0, %1, %2;" : "=l"(r) : "l"(a), "l"(b)); return r;
}
__device__ __forceinline__ u64t fma2(u64t a, u64t b, u64t c) {
    u64t r; asm("fma.rn.f32x2 %0, %1, %2, %3;" : "=l"(r) : "l"(a), "l"(b), "l"(c)); return r;
}

// Persistent kernel, 256 threads = 8 warps. STATIC strided item assignment
// (measured faster than dynamic ticketing in rounds 9/10). Smem combine
// buffers are ping-ponged by item parity so only ONE __syncthreads() per
// item is needed: the read-vs-next-write hazard on the same buffer is
// separated by the *following* item's barrier.
// Item = (pair p, 8-det tile). warp w owns i-eighth [w*64, w*64+64);
// lane: det = lane&7, phase = lane>>3; i = qb + 4k + phase, k in [0,16).
// One LDG.128 per sample yields taps for BOTH angles p and p+90.
__global__ void __launch_bounds__(256, 6) radon_kernel(float* __restrict__ out) {
    const int tid   = threadIdx.x;
    const int lane  = tid & 31;
    const int wrp   = tid >> 5;
    const int phase = lane >> 3;
    const int det   = lane & 7;
    const int qb    = wrp * 64;

    __shared__ float shA[2][8][8];
    __shared__ float shB[2][8][8];

    int par = 0;
    for (int it = blockIdx.x; it < ITEMS; it += BLOCKS, par ^= 1) {
        const int p     = it >> 6;
        const int tile8 = it & 63;
        const int j     = tile8 * 8 + det;

        const float4 A0 = g_ANG0[p];
        const float4 A1 = g_ANG1[p];
        const float x  = (float)j - C_HALF;
        const float au = A1.x, aw = A1.y;
        const float cu = fmaf(A0.x, x, A0.y);
        const float cw = fmaf(A0.z, x, A0.w);
        const uint4* __restrict__ P = (A1.z != 0.f) ? g_T : g_N;

        // exact-zero window: taps all zero unless u,w in [105,618).
        // Conservative slab [104,619]; skipped samples contribute exactly 0.
        float lo_i = (float)qb, hi_i = (float)(qb + 63);
        if (fabsf(au) > 1e-6f) {
            float inv = __frcp_rn(au);
            float t0 = (104.f - cu) * inv, t1 = (619.f - cu) * inv;
            lo_i = fmaxf(lo_i, fminf(t0, t1));
            hi_i = fminf(hi_i, fmaxf(t0, t1));
        }
        {
            float inv = __frcp_rn(aw);
            float t0 = (104.f - cw) * inv, t1 = (619.f - cw) * inv;
            lo_i = fmaxf(lo_i, fminf(t0, t1));
            hi_i = fminf(hi_i, fmaxf(t0, t1));
        }
        const int ilo = (int)lo_i;
        const int ihi = (int)hi_i + 1;
        const int klo = max(0, (ilo - qb - phase + 3) >> 2);
        const int khi = min(16, ((ihi - qb - phase) >> 2) + 1);
        const int is  = klo & ~7;
        const int ie  = min(16, (khi + 7) & ~7);

        const u64t AU2  = pk2(au, au);
        const u64t AW2  = pk2(aw, aw);
        const u64t CU2  = pk2(cu, cu);
        const u64t CW2  = pk2(cw, cw);
        const u64t STEP2= pk2(8.f, 8.f);
        const u64t MAG2 = pk2(8388607.5f, 8388607.5f);   // 2^23 - 0.5
        const u64t NM2  = pk2(-8388608.f, -8388608.f);   // -2^23
        const u64t NONE2= pk2(-1.f, -1.f);
        const u64t ONE2 = pk2(1.f, 1.f);

        const float i0f = (float)(qb + 4 * is + phase);
        u64t fi2 = pk2(i0f, i0f + 4.f);

        float fsA = 0.f, fsB = 0.f;

        for (int kb = is; kb < ie; kb += 8) {        // 8 samples per chunk
            __half2 accA = __float2half2_rn(0.f);
            __half2 accB = __float2half2_rn(0.f);
            #pragma unroll
            for (int q = 0; q < 4; ++q) {
                const u64t u2 = fma2(AU2, fi2, CU2);
                const u64t w2 = fma2(AW2, fi2, CW2);
                fi2 = add2(fi2, STEP2);

                const u64t ru2  = add2(u2, MAG2);         // 2^23 + floor(u)
                const u64t rw2  = add2(w2, MAG2);
                const u64t fku2 = add2(ru2, NM2);         // (float)floor(u)
                const u64t fkw2 = add2(rw2, NM2);
                const u64t wu2  = fma2(fku2, NONE2, u2);  // fraction
                const u64t ww2  = fma2(fkw2, NONE2, w2);
                const u64t omu2 = fma2(wu2, NONE2, ONE2); // 1 - frac
                const u64t omw2 = fma2(ww2, NONE2, ONE2);

                float rua, rub, rwa, rwb;  upk2(ru2, rua, rub);  upk2(rw2, rwa, rwb);
                float wua, wub, wwa, wwb;  upk2(wu2, wua, wub);  upk2(ww2, wwa, wwb);
                float oua, oub, owa, owb;  upk2(omu2, oua, oub); upk2(omw2, owa, owb);

                const int iua = __float_as_int(rua) & 0x7FFFFF;
                const int iub = __float_as_int(rub) & 0x7FFFFF;
                const int iwa = __float_as_int(rwa) & 0x7FFFFF;
                const int iwb = __float_as_int(rwb) & 0x7FFFFF;

                {   // sample A: one 16B load -> taps for both angles
                    const uint4 qq = __ldg(P + (iwa * W + iua));
                    const __half2 e01 = *reinterpret_cast<const __half2*>(&qq.x);
                    const __half2 e23 = *reinterpret_cast<const __half2*>(&qq.y);
                    const __half2 f01 = *reinterpret_cast<const __half2*>(&qq.z);
                    const __half2 f23 = *reinterpret_cast<const __half2*>(&qq.w);
                    const __half2 hw  = __floats2half2_rn(owa, wwa);   // (ow, ww)
                    const __half2 hp  = __floats2half2_rn(oua, wua);   // (ou, wu)
                    const __half2 wlo = __half2half2(__low2half(hw));
                    const __half2 whi = __half2half2(__high2half(hw));
                    accA = __hfma2(__hfma2(e01, wlo, __hmul2(e23, whi)), hp, accA);
                    accB = __hfma2(__hfma2(f01, wlo, __hmul2(f23, whi)), hp, accB);
                }
                {   // sample B
                    const uint4 qq = __ldg(P + (iwb * W + iub));
                    const __half2 e01 = *reinterpret_cast<const __half2*>(&qq.x);
                    const __half2 e23 = *reinterpret_cast<const __half2*>(&qq.y);
                    const __half2 f01 = *reinterpret_cast<const __half2*>(&qq.z);
                    const __half2 f23 = *reinterpret_cast<const __half2*>(&qq.w);
                    const __half2 hw  = __floats2half2_rn(owb, wwb);
                    const __half2 hp  = __floats2half2_rn(oub, wub);
                    const __half2 wlo = __half2half2(__low2half(hw));
                    const __half2 whi = __half2half2(__high2half(hw));
                    accA = __hfma2(__hfma2(e01, wlo, __hmul2(e23, whi)), hp, accA);
                    accB = __hfma2(__hfma2(f01, wlo, __hmul2(f23, whi)), hp, accB);
                }
            }
            const float2 fa = __half22float2(accA);
            const float2 fb = __half22float2(accB);
            fsA += fa.x + fa.y;
            fsB += fb.x + fb.y;
        }

        // combine the 4 phases (lanes differing in bits 3,4); fixed order
        fsA += __shfl_xor_sync(0xffffffffu, fsA, 8);
        fsA += __shfl_xor_sync(0xffffffffu, fsA, 16);
        fsB += __shfl_xor_sync(0xffffffffu, fsB, 8);
        fsB += __shfl_xor_sync(0xffffffffu, fsB, 16);

        if (lane < 8) { shA[par][wrp][lane] = fsA; shB[par][wrp][lane] = fsB; }
        __syncthreads();                 // single barrier per item (ping-pong)
        if (tid < 16) {
            const int which = tid >> 3, d = tid & 7;
            const int jj  = tile8 * 8 + d;
            const float* col = which ? &shB[par][0][0] : &shA[par][0][0];
            float s = col[0 * 8 + d];                // fixed order -> deterministic
            #pragma unroll
            for (int w2_ = 1; w2_ < 8; ++w2_) s += col[w2_ * 8 + d];
            out[jj * N_ANGLES + (which ? p + N_PAIRS : p)] = s;
        }
    }
}

extern "C" void kernel_launch(void* const* d_in, const int* in_sizes, int n_in,
                              void* d_out, int out_size) {
    const float* img    = (const float*)d_in[0];
    const int*   angles = (const int*)d_in[1];
    float*       out    = (float*)d_out;

    {
        dim3 block(256, 1, 1);
        dim3 grid((W + 31) / 32, (W + 31) / 32, 1);   // 23 x 23 tiles
        prep_kernel<<<grid, block>>>(img, angles);
    }
    radon_kernel<<<BLOCKS, 256>>>(out);
}